// round 2
// baseline (speedup 1.0000x reference)
#include <cuda_runtime.h>
#include <cuda_bf16.h>

// ---------------------------------------------------------------------------
// LRU forward on GB300, round 2: packed fp32x2 (FFMA2) GEMM inner loops.
//   Bu[b,l,n] = sum_h u[b,l,h] * (exp(gamma[n]) * (Bp_re[n,h] + i Bp_im[n,h]))
//   x[b,l,n]  = lam[n] * x[b,l-1,n] + Bu[b,l,n],  x[b,-1]=0
//   y[b,l,o]  = Re( sum_n x[b,l-1,n]*C[o,n] ) + sum_h u[b,l,h]*D[o,h]
// ---------------------------------------------------------------------------

#define BB   8
#define LL   8192
#define HH   128
#define NN   256
#define OO   128
#define TCH  128
#define NCH  (LL / TCH)   // 64
#define TS   16
#define K4S  (NN / 2)     // 128 state-pair K steps
#define K4U  (HH / 4)     // 32 u-quad K steps
#define K4T  (K4S + K4U)  // 160

typedef unsigned long long ull;

// packed fp32x2 fused multiply-add: d.lo += a.lo*b.lo ; d.hi += a.hi*b.hi
__device__ __forceinline__ void ffma2(ull& d, ull a, ull b) {
    asm("fma.rn.f32x2 %0, %1, %2, %0;" : "+l"(d) : "l"(a), "l"(b));
}
__device__ __forceinline__ float2 unpack2(ull v) {
    float2 r;
    asm("mov.b64 {%0, %1}, %2;" : "=f"(r.x), "=f"(r.y) : "l"(v));
    return r;
}

// ------------------------- scratch (static device) -------------------------
__device__ float2 g_Bu[(size_t)BB * LL * NN];        // 128 MiB
__device__ float2 g_Br2[(HH / 2) * NN];              // [hp][n] = (Bre[2hp,n],Bre[2hp+1,n])
__device__ float2 g_Bi2[(HH / 2) * NN];              // imag counterpart
__device__ float4 g_CD4[K4T * OO];                   // unified y-GEMM operand
__device__ float2 g_lam[NN];
__device__ float2 g_lamT[NN];
__device__ float2 g_end[BB * NCH * NN];
__device__ float2 g_carry[BB * NCH * NN];

// ------------------------------- prep ---------------------------------------
__global__ void prep_kernel(const float* __restrict__ nu_log,
                            const float* __restrict__ theta_log,
                            const float* __restrict__ gamma_log,
                            const float* __restrict__ Bp_re,
                            const float* __restrict__ Bp_im,
                            const float* __restrict__ C_re,
                            const float* __restrict__ C_im,
                            const float* __restrict__ D) {
    int idx = blockIdx.x * blockDim.x + threadIdx.x;   // 0..32767

    if (idx < NN) {
        float nu = expf(nu_log[idx]);
        float a  = expf(-nu);
        float th = expf(theta_log[idx]);
        g_lam[idx] = make_float2(a * cosf(th), a * sinf(th));
        double rT   = exp(-(double)nu * (double)TCH);
        double angT = (double)th * (double)TCH;
        g_lamT[idx] = make_float2((float)(rT * cos(angT)), (float)(rT * sin(angT)));
    }
    if (idx < (HH / 2) * NN) {           // packed B, h-pairs
        int hp = idx >> 8;
        int n  = idx & (NN - 1);
        float g = expf(gamma_log[n]);
        g_Br2[idx] = make_float2(g * Bp_re[n * HH + 2 * hp],
                                 g * Bp_re[n * HH + 2 * hp + 1]);
        g_Bi2[idx] = make_float2(g * Bp_im[n * HH + 2 * hp],
                                 g * Bp_im[n * HH + 2 * hp + 1]);
    }
    if (idx < K4T * OO) {                // unified C/D operand
        int k4 = idx >> 7;
        int o  = idx & (OO - 1);
        if (k4 < K4S) {
            int n0 = 2 * k4;
            g_CD4[idx] = make_float4( C_re[o * NN + n0],     -C_im[o * NN + n0],
                                      C_re[o * NN + n0 + 1], -C_im[o * NN + n0 + 1]);
        } else {
            int q = (k4 - K4S) * 4;
            g_CD4[idx] = make_float4(D[o * HH + q],     D[o * HH + q + 1],
                                     D[o * HH + q + 2], D[o * HH + q + 3]);
        }
    }
}

// -------------------- K1: Bu GEMM (f32x2) + local chunk scan -----------------
__global__ __launch_bounds__(256) void bu_scan_kernel(const float* __restrict__ u) {
    __shared__ __align__(16) float su[TS][HH];   // 8 KB

    const int c = blockIdx.x;
    const int b = blockIdx.y;
    const int n = threadIdx.x;

    const float2 lam = g_lam[n];
    float2 x = make_float2(0.f, 0.f);
    const int l0 = c * TCH;
    const float* ub = u + ((size_t)b * LL + l0) * HH;

    for (int sub = 0; sub < TCH / TS; ++sub) {
        __syncthreads();
        {
            const float4* src = (const float4*)(ub + (size_t)sub * TS * HH);
            float4* dst = (float4*)&su[0][0];
            #pragma unroll
            for (int i = 0; i < (TS * HH / 4) / 256; ++i)
                dst[n + i * 256] = src[n + i * 256];
        }
        __syncthreads();

        // acc.lo accumulates even-h terms, acc.hi odd-h terms
        ull ar[TS], ai[TS];
        #pragma unroll
        for (int j = 0; j < TS; ++j) { ar[j] = 0ull; ai[j] = 0ull; }

        #pragma unroll 2
        for (int hp2 = 0; hp2 < HH / 4; ++hp2) {       // 4 h per iter = 2 h-pairs
            ull br0 = *(const ull*)&g_Br2[(2 * hp2) * NN + n];
            ull br1 = *(const ull*)&g_Br2[(2 * hp2 + 1) * NN + n];
            ull bi0 = *(const ull*)&g_Bi2[(2 * hp2) * NN + n];
            ull bi1 = *(const ull*)&g_Bi2[(2 * hp2 + 1) * NN + n];
            #pragma unroll
            for (int j = 0; j < TS; ++j) {
                ulonglong2 a = *(const ulonglong2*)&su[j][hp2 * 4];  // broadcast
                ffma2(ar[j], a.x, br0);
                ffma2(ai[j], a.x, bi0);
                ffma2(ar[j], a.y, br1);
                ffma2(ai[j], a.y, bi1);
            }
        }

        size_t base = ((size_t)b * LL + l0 + sub * TS) * NN + n;
        #pragma unroll
        for (int j = 0; j < TS; ++j) {
            float2 vr = unpack2(ar[j]);
            float2 vi = unpack2(ai[j]);
            float2 v  = make_float2(vr.x + vr.y, vi.x + vi.y);
            g_Bu[base + (size_t)j * NN] = v;
            float nr = fmaf(lam.x, x.x, fmaf(-lam.y, x.y, v.x));
            float ni = fmaf(lam.x, x.y, fmaf( lam.y, x.x, v.y));
            x = make_float2(nr, ni);
        }
    }
    g_end[((size_t)b * NCH + c) * NN + n] = x;
}

// ----------------- K2: combine chunk ends -> per-chunk carries ---------------
__global__ void carry_kernel() {
    const int b = blockIdx.x;
    const int n = threadIdx.x;
    const float2 lamT = g_lamT[n];
    float2 x = make_float2(0.f, 0.f);
    for (int ch = 0; ch < NCH; ++ch) {
        size_t i = ((size_t)b * NCH + ch) * NN + n;
        g_carry[i] = x;
        float2 e = g_end[i];
        float nr = fmaf(lamT.x, x.x, fmaf(-lamT.y, x.y, e.x));
        float ni = fmaf(lamT.x, x.y, fmaf( lamT.y, x.x, e.y));
        x = make_float2(nr, ni);
    }
}

// --------- K3: final scan + states output + fused y projection (f32x2) -------
__global__ __launch_bounds__(256) void out_kernel(const float* __restrict__ u,
                                                  float* __restrict__ yout,
                                                  float2* __restrict__ stc,
                                                  float* __restrict__ str) {
    __shared__ __align__(16) float2 pre2[TS][NN];   // 32 KB  (re, im) pre-states
    __shared__ __align__(16) float  su[TS][HH];     //  8 KB

    const int c   = blockIdx.x;
    const int b   = blockIdx.y;
    const int tid = threadIdx.x;
    const int n   = tid;
    const int o   = tid & (OO - 1);
    const int jg  = tid >> 7;          // 0/1 -> timesteps [jg*8, jg*8+8)

    const float2 lam = g_lam[n];
    float2 x = g_carry[((size_t)b * NCH + c) * NN + n];
    const int l0 = c * TCH;

    for (int sub = 0; sub < TCH / TS; ++sub) {
        const int lbase = l0 + sub * TS;
        __syncthreads();
        {
            const float4* src = (const float4*)(u + ((size_t)b * LL + lbase) * HH);
            float4* dst = (float4*)&su[0][0];
            #pragma unroll
            for (int i = 0; i < (TS * HH / 4) / 256; ++i)
                dst[tid + i * 256] = src[tid + i * 256];
        }
        // scan: publish pre-states, write states output if requested
        {
            size_t bub = ((size_t)b * LL + lbase) * NN + n;
            size_t stb = ((size_t)b * (LL + 1) + lbase) * NN + n;
            #pragma unroll
            for (int j = 0; j < TS; ++j) {
                pre2[j][n] = x;
                if (stc) stc[stb + (size_t)j * NN] = x;
                if (str) str[stb + (size_t)j * NN] = x.x;
                float2 v = g_Bu[bub + (size_t)j * NN];
                float nr = fmaf(lam.x, x.x, fmaf(-lam.y, x.y, v.x));
                float ni = fmaf(lam.x, x.y, fmaf( lam.y, x.x, v.y));
                x = make_float2(nr, ni);
            }
        }
        __syncthreads();

        if (yout) {
            ull a0[8], a1[8];
            #pragma unroll
            for (int j = 0; j < 8; ++j) { a0[j] = 0ull; a1[j] = 0ull; }

            // state part: acc += (re,im) .* (Cre,-Cim)
            #pragma unroll 4
            for (int k4 = 0; k4 < K4S; ++k4) {
                ulonglong2 bv = *(const ulonglong2*)&g_CD4[k4 * OO + o];
                #pragma unroll
                for (int j = 0; j < 8; ++j) {
                    ulonglong2 av = *(const ulonglong2*)&pre2[jg * 8 + j][2 * k4];
                    ffma2(a0[j], av.x, bv.x);
                    ffma2(a1[j], av.y, bv.y);
                }
            }
            // u part: acc += (u0..u3) .* (d0..d3)
            #pragma unroll 4
            for (int k4 = 0; k4 < K4U; ++k4) {
                ulonglong2 bv = *(const ulonglong2*)&g_CD4[(K4S + k4) * OO + o];
                #pragma unroll
                for (int j = 0; j < 8; ++j) {
                    ulonglong2 av = *(const ulonglong2*)&su[jg * 8 + j][k4 * 4];
                    ffma2(a0[j], av.x, bv.x);
                    ffma2(a1[j], av.y, bv.y);
                }
            }
            #pragma unroll
            for (int j = 0; j < 8; ++j) {
                float2 f0 = unpack2(a0[j]);
                float2 f1 = unpack2(a1[j]);
                int l = lbase + jg * 8 + j;
                yout[((size_t)b * LL + l) * OO + o] = (f0.x + f0.y) + (f1.x + f1.y);
            }
        }
    }

    if (c == NCH - 1) {
        if (stc) stc[((size_t)b * (LL + 1) + LL) * NN + n] = x;
        if (str) str[((size_t)b * (LL + 1) + LL) * NN + n] = x.x;
    }
}

// ------------------------------ launch ---------------------------------------
extern "C" void kernel_launch(void* const* d_in, const int* in_sizes, int n_in,
                              void* d_out, int out_size) {
    const float* u         = (const float*)d_in[0];
    const float* nu_log    = (const float*)d_in[1];
    const float* theta_log = (const float*)d_in[2];
    const float* gamma_log = (const float*)d_in[3];
    const float* Bp_re     = (const float*)d_in[4];
    const float* Bp_im     = (const float*)d_in[5];
    const float* C_re      = (const float*)d_in[6];
    const float* C_im      = (const float*)d_in[7];
    const float* D         = (const float*)d_in[8];

    float* out = (float*)d_out;

    const long long NY  = (long long)BB * LL * OO;
    const long long NSc = (long long)BB * (LL + 1) * NN;
    const long long osz = (long long)out_size;

    float*  yout = nullptr;
    float2* stc  = nullptr;
    float*  str  = nullptr;

    if (osz == NY) {
        yout = out;
    } else if (osz == NY + 2 * NSc) {
        yout = out; stc = (float2*)(out + NY);
    } else if (osz == 2 * NSc) {
        stc = (float2*)out;
    } else if (osz == NSc) {
        stc = (float2*)out;
    } else if (osz == NY + NSc) {
        yout = out; str = out + NY;
    } else {
        yout = out;
    }

    prep_kernel<<<128, 256>>>(nu_log, theta_log, gamma_log,
                              Bp_re, Bp_im, C_re, C_im, D);
    bu_scan_kernel<<<dim3(NCH, BB), 256>>>(u);
    carry_kernel<<<BB, 256>>>();
    out_kernel<<<dim3(NCH, BB), 256>>>(u, yout, stc, str);
}

// round 4
// speedup vs baseline: 2.5147x; 2.5147x over previous
#include <cuda_runtime.h>
#include <cuda_bf16.h>
#include <cstdint>

// ---------------------------------------------------------------------------
// LRU forward on GB300, round 4: warp-level mma.sync (bf16 3-split) GEMMs +
// fp32 chunked scan. No tcgen05 (harness targets plain sm_103).
//
//   GEMM1: Bu[l, 0..511] = U[l,:] @ B1^T     (cols = states, re/im interleaved)
//   ends/carry/scan: fp32 recurrence; pre-states -> output or scratch
//   GEMM2: y[l,o] = Pre[l,0..511] @ C~^T + U[l,:] @ D^T     (K = 640, 5 chunks)
// ---------------------------------------------------------------------------

#define BB   8
#define LL   8192
#define HH   128
#define NN   256
#define OO   128
#define TCH  128
#define NCH  (LL / TCH)   // 64

#define STR  66           // smem row stride in u32 (64 k-pairs + pad)
// smem layout (u32 units)
#define O_AH 0
#define O_AL (128 * STR)
#define O_BH (2 * 128 * STR)
#define O_BL (2 * 128 * STR + 64 * STR)
#define SMEM_U32 (2 * 128 * STR + 2 * 64 * STR)      // 25344 u32
#define SMEM_B   (SMEM_U32 * 4)                      // 101376 bytes

// ------------------------- scratch (static device) -------------------------
__device__ float    g_BuF[(size_t)BB * LL * 512];    // 134 MB, (re,im) interleaved
__device__ float2   g_states[(size_t)BB * LL * NN];  // 128 MB pre-states fallback
__device__ float2   g_lam[NN];
__device__ float2   g_lamT[NN];
__device__ float2   g_end[BB * NCH * NN];
__device__ float2   g_carry[BB * NCH * NN];
// pre-packed, k-pair-permuted B images (u32 = bf16x2)
__device__ uint32_t g_B1h[512 * 64];
__device__ uint32_t g_B1l[512 * 64];
__device__ uint32_t g_B2h[5 * 128 * 64];
__device__ uint32_t g_B2l[5 * 128 * 64];

// ------------------------------ helpers -------------------------------------
// permuted k-pair index: within an 8-pair (k16) block, pair p -> (p&3)*2 + (p>>2)
__device__ __forceinline__ int kkperm(int ps) {
    return (ps & ~7) + ((ps & 3) * 2 + ((ps >> 2) & 1));
}

__device__ __forceinline__ void split_pair(float v0, float v1,
                                           uint32_t& hi, uint32_t& lo) {
    __nv_bfloat16 h0 = __float2bfloat16(v0);
    __nv_bfloat16 h1 = __float2bfloat16(v1);
    __nv_bfloat16 l0 = __float2bfloat16(v0 - __bfloat162float(h0));
    __nv_bfloat16 l1 = __float2bfloat16(v1 - __bfloat162float(h1));
    hi = (uint32_t)__bfloat16_as_ushort(h0) | ((uint32_t)__bfloat16_as_ushort(h1) << 16);
    lo = (uint32_t)__bfloat16_as_ushort(l0) | ((uint32_t)__bfloat16_as_ushort(l1) << 16);
}

__device__ __forceinline__ void mma16816(float* d,
                                         uint32_t a0, uint32_t a1, uint32_t a2, uint32_t a3,
                                         uint32_t b0, uint32_t b1) {
    asm volatile("mma.sync.aligned.m16n8k16.row.col.f32.bf16.bf16.f32 "
                 "{%0,%1,%2,%3},{%4,%5,%6,%7},{%8,%9},{%0,%1,%2,%3};"
                 : "+f"(d[0]), "+f"(d[1]), "+f"(d[2]), "+f"(d[3])
                 : "r"(a0), "r"(a1), "r"(a2), "r"(a3), "r"(b0), "r"(b1));
}

__device__ __forceinline__ uint2 lds64(const uint32_t* p) {
    return *(const uint2*)p;
}

// ------------------------------- prep ---------------------------------------
__global__ void prep_kernel(const float* __restrict__ nu_log,
                            const float* __restrict__ theta_log,
                            const float* __restrict__ gamma_log,
                            const float* __restrict__ Bp_re,
                            const float* __restrict__ Bp_im,
                            const float* __restrict__ C_re,
                            const float* __restrict__ C_im,
                            const float* __restrict__ D) {
    int idx = blockIdx.x * blockDim.x + threadIdx.x;   // 0..49151

    if (idx < NN) {
        float nu = expf(nu_log[idx]);
        float a  = expf(-nu);
        float th = expf(theta_log[idx]);
        g_lam[idx] = make_float2(a * cosf(th), a * sinf(th));
        double rT   = exp(-(double)nu * (double)TCH);
        double angT = (double)th * (double)TCH;
        g_lamT[idx] = make_float2((float)(rT * cos(angT)), (float)(rT * sin(angT)));
    }
    // B1: 512 rows (r = 2n+im) x 64 k-pairs
    if (idx < 512 * 64) {
        int r  = idx >> 6;
        int ps = idx & 63;
        int n  = r >> 1;
        int im = r & 1;
        float g = expf(gamma_log[n]);
        const float* src = im ? Bp_im : Bp_re;
        float v0 = g * src[n * HH + 2 * ps];
        float v1 = g * src[n * HH + 2 * ps + 1];
        uint32_t hi, lo;
        split_pair(v0, v1, hi, lo);
        int d = r * 64 + kkperm(ps);
        g_B1h[d] = hi;
        g_B1l[d] = lo;
    }
    // B2: 5 k-chunks x 128 rows (o) x 64 k-pairs
    if (idx < 5 * 128 * 64) {
        int c  = idx >> 13;
        int o  = (idx >> 6) & 127;
        int ps = idx & 63;
        float v0, v1;
        if (c < 4) {
            v0 =  C_re[o * NN + c * 64 + ps];
            v1 = -C_im[o * NN + c * 64 + ps];
        } else {
            v0 = D[o * HH + 2 * ps];
            v1 = D[o * HH + 2 * ps + 1];
        }
        uint32_t hi, lo;
        split_pair(v0, v1, hi, lo);
        int d = (c * 128 + o) * 64 + kkperm(ps);
        g_B2h[d] = hi;
        g_B2l[d] = lo;
    }
}

// ------------------- GEMM1: Bu = U @ B1^T  (mma.sync, 3x bf16) ---------------
__global__ __launch_bounds__(256, 2) void gemm1_kernel(const float* __restrict__ u) {
    extern __shared__ uint32_t sm[];
    uint32_t* Ah = sm + O_AH;
    uint32_t* Al = sm + O_AL;
    uint32_t* Bh = sm + O_BH;
    uint32_t* Bl = sm + O_BL;

    const int lt   = blockIdx.x;
    const int b    = blockIdx.y;
    const int tid  = threadIdx.x;
    const int wid  = tid >> 5;
    const int lane = tid & 31;
    const int g    = lane >> 2;
    const int tq   = lane & 3;
    const int l0   = lt * 128;
    const int wr   = (wid & 3) * 32;     // warp row base (of 128)
    const int wc   = (wid >> 2) * 32;    // warp col base (of 64-chunk)

    // pack A tile: U[128 l x 128 h] -> hi/lo bf16x2, permuted
    {
        const float* ut = u + ((size_t)b * LL + l0) * HH;
        #pragma unroll
        for (int i = 0; i < 32; ++i) {
            int p  = tid + 256 * i;         // 8192
            int row = p >> 6, ps = p & 63;
            float2 v = *(const float2*)(ut + row * HH + 2 * ps);
            uint32_t hi, lo;
            split_pair(v.x, v.y, hi, lo);
            int kk = kkperm(ps);
            Ah[row * STR + kk] = hi;
            Al[row * STR + kk] = lo;
        }
    }
    __syncthreads();

    for (int cc = 0; cc < 8; ++cc) {
        // load B col-chunk (64 cols x 64 kk), already permuted in global
        {
            const uint32_t* gh = g_B1h + cc * 64 * 64;
            const uint32_t* gl = g_B1l + cc * 64 * 64;
            #pragma unroll
            for (int i = 0; i < 16; ++i) {
                int p = tid + 256 * i;      // 4096
                int col = p >> 6, kk = p & 63;
                Bh[col * STR + kk] = gh[p];
                Bl[col * STR + kk] = gl[p];
            }
        }
        __syncthreads();

        float acc[2][4][4];
        #pragma unroll
        for (int mf = 0; mf < 2; ++mf)
            #pragma unroll
            for (int nf = 0; nf < 4; ++nf)
                #pragma unroll
                for (int q = 0; q < 4; ++q) acc[mf][nf][q] = 0.f;

        #pragma unroll 1
        for (int K = 0; K < 8; ++K) {
            const int kb = K * 8 + 2 * tq;
            uint32_t ah[2][4], al[2][4];
            #pragma unroll
            for (int mf = 0; mf < 2; ++mf) {
                int r = wr + mf * 16 + g;
                uint2 t0 = lds64(&Ah[r * STR + kb]);
                uint2 t1 = lds64(&Ah[(r + 8) * STR + kb]);
                ah[mf][0] = t0.x; ah[mf][2] = t0.y;
                ah[mf][1] = t1.x; ah[mf][3] = t1.y;
                uint2 s0 = lds64(&Al[r * STR + kb]);
                uint2 s1 = lds64(&Al[(r + 8) * STR + kb]);
                al[mf][0] = s0.x; al[mf][2] = s0.y;
                al[mf][1] = s1.x; al[mf][3] = s1.y;
            }
            #pragma unroll
            for (int nf = 0; nf < 4; ++nf) {
                int cr = wc + nf * 8 + g;
                uint2 bh = lds64(&Bh[cr * STR + kb]);
                uint2 bl = lds64(&Bl[cr * STR + kb]);
                #pragma unroll
                for (int mf = 0; mf < 2; ++mf) {
                    mma16816(acc[mf][nf], ah[mf][0], ah[mf][1], ah[mf][2], ah[mf][3], bh.x, bh.y);
                    mma16816(acc[mf][nf], ah[mf][0], ah[mf][1], ah[mf][2], ah[mf][3], bl.x, bl.y);
                    mma16816(acc[mf][nf], al[mf][0], al[mf][1], al[mf][2], al[mf][3], bh.x, bh.y);
                }
            }
        }

        // epilogue: (re,im) pairs -> g_BuF
        {
            float* dst = g_BuF + ((size_t)b * LL + l0) * 512 + cc * 64;
            #pragma unroll
            for (int mf = 0; mf < 2; ++mf) {
                int row = wr + mf * 16 + g;
                #pragma unroll
                for (int nf = 0; nf < 4; ++nf) {
                    int col = wc + nf * 8 + 2 * tq;
                    *(float2*)&dst[(size_t)row * 512 + col] =
                        make_float2(acc[mf][nf][0], acc[mf][nf][1]);
                    *(float2*)&dst[(size_t)(row + 8) * 512 + col] =
                        make_float2(acc[mf][nf][2], acc[mf][nf][3]);
                }
            }
        }
        __syncthreads();
    }
}

// --------------------- ends: local chunk-end states --------------------------
__global__ __launch_bounds__(256) void ends_kernel() {
    const int c = blockIdx.x;
    const int b = blockIdx.y;
    const int n = threadIdx.x;
    const float2 lam = g_lam[n];
    float2 x = make_float2(0.f, 0.f);
    const float2* bu = (const float2*)g_BuF + ((size_t)b * LL + c * TCH) * NN + n;
    #pragma unroll 4
    for (int j = 0; j < TCH; ++j) {
        float2 v = bu[(size_t)j * NN];
        float nr = fmaf(lam.x, x.x, fmaf(-lam.y, x.y, v.x));
        float ni = fmaf(lam.x, x.y, fmaf( lam.y, x.x, v.y));
        x = make_float2(nr, ni);
    }
    g_end[((size_t)b * NCH + c) * NN + n] = x;
}

// ----------------- carry: combine chunk ends -> carries ----------------------
__global__ void carry_kernel() {
    const int b = blockIdx.x;
    const int n = threadIdx.x;
    const float2 lamT = g_lamT[n];
    float2 x = make_float2(0.f, 0.f);
    for (int ch = 0; ch < NCH; ++ch) {
        size_t i = ((size_t)b * NCH + ch) * NN + n;
        g_carry[i] = x;
        float2 e = g_end[i];
        float nr = fmaf(lamT.x, x.x, fmaf(-lamT.y, x.y, e.x));
        float ni = fmaf(lamT.x, x.y, fmaf( lamT.y, x.x, e.y));
        x = make_float2(nr, ni);
    }
}

// ----------------- scan: final scan, write pre-states ------------------------
__global__ __launch_bounds__(256) void scan_kernel(float2* __restrict__ preOut,
                                                   size_t bstr,
                                                   float* __restrict__ str,
                                                   int writeFinal) {
    const int c = blockIdx.x;
    const int b = blockIdx.y;
    const int n = threadIdx.x;
    const float2 lam = g_lam[n];
    float2 x = g_carry[((size_t)b * NCH + c) * NN + n];
    const int l0 = c * TCH;
    const float2* bu = (const float2*)g_BuF + ((size_t)b * LL + l0) * NN + n;
    float2* po = preOut + ((size_t)b * bstr + l0) * NN + n;
    float*  so = str ? str + ((size_t)b * (LL + 1) + l0) * NN + n : nullptr;
    #pragma unroll 4
    for (int j = 0; j < TCH; ++j) {
        po[(size_t)j * NN] = x;
        if (so) so[(size_t)j * NN] = x.x;
        float2 v = bu[(size_t)j * NN];
        float nr = fmaf(lam.x, x.x, fmaf(-lam.y, x.y, v.x));
        float ni = fmaf(lam.x, x.y, fmaf( lam.y, x.x, v.y));
        x = make_float2(nr, ni);
    }
    if (c == NCH - 1) {
        if (writeFinal) po[(size_t)TCH * NN] = x;
        if (so) so[(size_t)TCH * NN] = x.x;
    }
}

// ------------- GEMM2: y = Pre @ C~^T + U @ D^T  (mma.sync, 3x bf16) ----------
__global__ __launch_bounds__(256, 2) void gemm2_kernel(const float* __restrict__ u,
                                                       const float* __restrict__ preF,
                                                       size_t bstr,
                                                       float* __restrict__ yout) {
    extern __shared__ uint32_t sm[];
    uint32_t* Ah = sm + O_AH;
    uint32_t* Al = sm + O_AL;
    uint32_t* Bh = sm + O_BH;
    uint32_t* Bl = sm + O_BL;

    const int lt   = blockIdx.x;
    const int b    = blockIdx.y;
    const int tid  = threadIdx.x;
    const int wid  = tid >> 5;
    const int lane = tid & 31;
    const int g    = lane >> 2;
    const int tq   = lane & 3;
    const int l0   = lt * 128;
    const int wr   = (wid & 3) * 32;
    const int wc   = (wid >> 2) * 32;

    float acc[2][2][4][4];    // [col-chunk][mf][nf][quad]
    #pragma unroll
    for (int cc = 0; cc < 2; ++cc)
        #pragma unroll
        for (int mf = 0; mf < 2; ++mf)
            #pragma unroll
            for (int nf = 0; nf < 4; ++nf)
                #pragma unroll
                for (int q = 0; q < 4; ++q) acc[cc][mf][nf][q] = 0.f;

    for (int kc = 0; kc < 5; ++kc) {
        // pack A chunk: pre-states (kc<4) or u (kc==4)
        {
            #pragma unroll
            for (int i = 0; i < 32; ++i) {
                int p = tid + 256 * i;
                int row = p >> 6, ps = p & 63;
                float2 v;
                if (kc < 4)
                    v = *(const float2*)(preF + ((size_t)b * bstr + l0 + row) * 512
                                         + kc * 128 + 2 * ps);
                else
                    v = *(const float2*)(u + ((size_t)b * LL + l0 + row) * HH + 2 * ps);
                uint32_t hi, lo;
                split_pair(v.x, v.y, hi, lo);
                int kk = kkperm(ps);
                Ah[row * STR + kk] = hi;
                Al[row * STR + kk] = lo;
            }
        }
        for (int cc = 0; cc < 2; ++cc) {
            // load B chunk [kc][cc]
            {
                const uint32_t* gh = g_B2h + (kc * 128 + cc * 64) * 64;
                const uint32_t* gl = g_B2l + (kc * 128 + cc * 64) * 64;
                #pragma unroll
                for (int i = 0; i < 16; ++i) {
                    int p = tid + 256 * i;
                    int col = p >> 6, kk = p & 63;
                    Bh[col * STR + kk] = gh[p];
                    Bl[col * STR + kk] = gl[p];
                }
            }
            __syncthreads();

            #pragma unroll 1
            for (int K = 0; K < 8; ++K) {
                const int kb = K * 8 + 2 * tq;
                uint32_t ah[2][4], al[2][4];
                #pragma unroll
                for (int mf = 0; mf < 2; ++mf) {
                    int r = wr + mf * 16 + g;
                    uint2 t0 = lds64(&Ah[r * STR + kb]);
                    uint2 t1 = lds64(&Ah[(r + 8) * STR + kb]);
                    ah[mf][0] = t0.x; ah[mf][2] = t0.y;
                    ah[mf][1] = t1.x; ah[mf][3] = t1.y;
                    uint2 s0 = lds64(&Al[r * STR + kb]);
                    uint2 s1 = lds64(&Al[(r + 8) * STR + kb]);
                    al[mf][0] = s0.x; al[mf][2] = s0.y;
                    al[mf][1] = s1.x; al[mf][3] = s1.y;
                }
                #pragma unroll
                for (int nf = 0; nf < 4; ++nf) {
                    int cr = wc + nf * 8 + g;
                    uint2 bh = lds64(&Bh[cr * STR + kb]);
                    uint2 bl = lds64(&Bl[cr * STR + kb]);
                    #pragma unroll
                    for (int mf = 0; mf < 2; ++mf) {
                        mma16816(acc[cc][mf][nf], ah[mf][0], ah[mf][1], ah[mf][2], ah[mf][3], bh.x, bh.y);
                        mma16816(acc[cc][mf][nf], ah[mf][0], ah[mf][1], ah[mf][2], ah[mf][3], bl.x, bl.y);
                        mma16816(acc[cc][mf][nf], al[mf][0], al[mf][1], al[mf][2], al[mf][3], bh.x, bh.y);
                    }
                }
            }
            __syncthreads();   // B (and A at loop end) safe to overwrite
        }
    }

    // epilogue: y
    {
        float* dst = yout + ((size_t)b * LL + l0) * OO;
        #pragma unroll
        for (int cc = 0; cc < 2; ++cc)
            #pragma unroll
            for (int mf = 0; mf < 2; ++mf) {
                int row = wr + mf * 16 + g;
                #pragma unroll
                for (int nf = 0; nf < 4; ++nf) {
                    int col = cc * 64 + wc + nf * 8 + 2 * tq;
                    *(float2*)&dst[(size_t)row * OO + col] =
                        make_float2(acc[cc][mf][nf][0], acc[cc][mf][nf][1]);
                    *(float2*)&dst[(size_t)(row + 8) * OO + col] =
                        make_float2(acc[cc][mf][nf][2], acc[cc][mf][nf][3]);
                }
            }
    }
}

// ------------------------------ launch ---------------------------------------
extern "C" void kernel_launch(void* const* d_in, const int* in_sizes, int n_in,
                              void* d_out, int out_size) {
    const float* u         = (const float*)d_in[0];
    const float* nu_log    = (const float*)d_in[1];
    const float* theta_log = (const float*)d_in[2];
    const float* gamma_log = (const float*)d_in[3];
    const float* Bp_re     = (const float*)d_in[4];
    const float* Bp_im     = (const float*)d_in[5];
    const float* C_re      = (const float*)d_in[6];
    const float* C_im      = (const float*)d_in[7];
    const float* D         = (const float*)d_in[8];

    float* out = (float*)d_out;

    const long long NY  = (long long)BB * LL * OO;
    const long long NSc = (long long)BB * (LL + 1) * NN;
    const long long osz = (long long)out_size;

    float*  yout = nullptr;
    float2* stc  = nullptr;   // complex states output
    float*  str  = nullptr;   // real-only states output

    if (osz == NY) {
        yout = out;
    } else if (osz == NY + 2 * NSc) {
        yout = out; stc = (float2*)(out + NY);
    } else if (osz == 2 * NSc) {
        stc = (float2*)out;
    } else if (osz == NSc) {
        stc = (float2*)out;
    } else if (osz == NY + NSc) {
        yout = out; str = out + NY;
    } else {
        yout = out;
    }

    static int smem_set = 0;
    if (!smem_set) {
        cudaFuncSetAttribute(gemm1_kernel, cudaFuncAttributeMaxDynamicSharedMemorySize, SMEM_B);
        cudaFuncSetAttribute(gemm2_kernel, cudaFuncAttributeMaxDynamicSharedMemorySize, SMEM_B);
        smem_set = 1;
    }

    prep_kernel<<<192, 256>>>(nu_log, theta_log, gamma_log,
                              Bp_re, Bp_im, C_re, C_im, D);
    gemm1_kernel<<<dim3(LL / 128, BB), 256, SMEM_B>>>(u);
    ends_kernel<<<dim3(NCH, BB), 256>>>();
    carry_kernel<<<BB, 256>>>();

    // pre-states destination: complex states output if present, else scratch
    float2* preDev;
    size_t  bstr;
    if (stc) {
        preDev = stc;
        bstr   = (size_t)(LL + 1);
    } else {
        void* p = nullptr;
        cudaGetSymbolAddress(&p, g_states);
        preDev = (float2*)p;
        bstr   = (size_t)LL;
    }

    scan_kernel<<<dim3(NCH, BB), 256>>>(preDev, bstr, str, stc ? 1 : 0);

    if (yout)
        gemm2_kernel<<<dim3(LL / 128, BB), 256, SMEM_B>>>(u, (const float*)preDev,
                                                          bstr, yout);
}

// round 5
// speedup vs baseline: 2.6446x; 1.0517x over previous
#include <cuda_runtime.h>
#include <cuda_bf16.h>
#include <cstdint>

// ---------------------------------------------------------------------------
// LRU forward on GB300, round 5: mma.sync bf16-3-split GEMMs + fused scan glue.
//   gemm1: Bu = U @ B1^T  (+ fused per-chunk local scan -> g_end)
//   scan:  carry prologue (lamT-power weighted sum of ends) + final scan,
//          writes pre-states to output/scratch
//   gemm2: y = Pre @ C~^T + U @ D^T   (K = 640, 5 chunks)
// ---------------------------------------------------------------------------

#define BB   8
#define LL   8192
#define HH   128
#define NN   256
#define OO   128
#define TCH  128
#define NCH  (LL / TCH)   // 64

#define STR  66           // smem row stride in u32 (64 k-pairs + pad)
#define O_AH 0
#define O_AL (128 * STR)
#define O_BH (2 * 128 * STR)
#define O_BL (2 * 128 * STR + 64 * STR)
#define SMEM_U32 (2 * 128 * STR + 2 * 64 * STR)
#define SMEM_B   (SMEM_U32 * 4)                      // 101376 bytes

// ------------------------- scratch (static device) -------------------------
__device__ float    g_BuF[(size_t)BB * LL * 512];    // 134 MB, (re,im) interleaved
__device__ float2   g_states[(size_t)BB * LL * NN];  // 128 MB pre-states fallback
__device__ float2   g_lam[NN];
__device__ float2   g_lamP[NCH * NN];                // lamT^k, k = 0..63
__device__ float2   g_end[BB * NCH * NN];
// pre-packed, k-pair-permuted B images (u32 = bf16x2)
__device__ uint32_t g_B1h[512 * 64];
__device__ uint32_t g_B1l[512 * 64];
__device__ uint32_t g_B2h[5 * 128 * 64];
__device__ uint32_t g_B2l[5 * 128 * 64];

// ------------------------------ helpers -------------------------------------
__device__ __forceinline__ int kkperm(int ps) {
    return (ps & ~7) + ((ps & 3) * 2 + ((ps >> 2) & 1));
}

__device__ __forceinline__ void split_pair(float v0, float v1,
                                           uint32_t& hi, uint32_t& lo) {
    __nv_bfloat16 h0 = __float2bfloat16(v0);
    __nv_bfloat16 h1 = __float2bfloat16(v1);
    __nv_bfloat16 l0 = __float2bfloat16(v0 - __bfloat162float(h0));
    __nv_bfloat16 l1 = __float2bfloat16(v1 - __bfloat162float(h1));
    hi = (uint32_t)__bfloat16_as_ushort(h0) | ((uint32_t)__bfloat16_as_ushort(h1) << 16);
    lo = (uint32_t)__bfloat16_as_ushort(l0) | ((uint32_t)__bfloat16_as_ushort(l1) << 16);
}

__device__ __forceinline__ void mma16816(float* d,
                                         uint32_t a0, uint32_t a1, uint32_t a2, uint32_t a3,
                                         uint32_t b0, uint32_t b1) {
    asm volatile("mma.sync.aligned.m16n8k16.row.col.f32.bf16.bf16.f32 "
                 "{%0,%1,%2,%3},{%4,%5,%6,%7},{%8,%9},{%0,%1,%2,%3};"
                 : "+f"(d[0]), "+f"(d[1]), "+f"(d[2]), "+f"(d[3])
                 : "r"(a0), "r"(a1), "r"(a2), "r"(a3), "r"(b0), "r"(b1));
}

__device__ __forceinline__ uint2 lds64(const uint32_t* p) {
    return *(const uint2*)p;
}

// ------------------------------- prep ---------------------------------------
__global__ void prep_kernel(const float* __restrict__ nu_log,
                            const float* __restrict__ theta_log,
                            const float* __restrict__ gamma_log,
                            const float* __restrict__ Bp_re,
                            const float* __restrict__ Bp_im,
                            const float* __restrict__ C_re,
                            const float* __restrict__ C_im,
                            const float* __restrict__ D) {
    int idx = blockIdx.x * blockDim.x + threadIdx.x;   // 0..49151

    if (idx < NN) {
        float nu = expf(nu_log[idx]);
        float a  = expf(-nu);
        float th = expf(theta_log[idx]);
        g_lam[idx] = make_float2(a * cosf(th), a * sinf(th));
    }
    // lamT^k table (double-precision powers)
    if (idx < NCH * NN) {
        int k = idx >> 8;
        int n = idx & (NN - 1);
        double nu = exp((double)nu_log[n]);
        double th = exp((double)theta_log[n]);
        double r   = exp(-nu * (double)TCH * (double)k);
        double ang = th * (double)TCH * (double)k;
        g_lamP[idx] = make_float2((float)(r * cos(ang)), (float)(r * sin(ang)));
    }
    // B1: 512 rows (r = 2n+im) x 64 k-pairs
    if (idx < 512 * 64) {
        int r  = idx >> 6;
        int ps = idx & 63;
        int n  = r >> 1;
        int im = r & 1;
        float g = expf(gamma_log[n]);
        const float* src = im ? Bp_im : Bp_re;
        float v0 = g * src[n * HH + 2 * ps];
        float v1 = g * src[n * HH + 2 * ps + 1];
        uint32_t hi, lo;
        split_pair(v0, v1, hi, lo);
        int d = r * 64 + kkperm(ps);
        g_B1h[d] = hi;
        g_B1l[d] = lo;
    }
    // B2: 5 k-chunks x 128 rows (o) x 64 k-pairs
    if (idx < 5 * 128 * 64) {
        int c  = idx >> 13;
        int o  = (idx >> 6) & 127;
        int ps = idx & 63;
        float v0, v1;
        if (c < 4) {
            v0 =  C_re[o * NN + c * 64 + ps];
            v1 = -C_im[o * NN + c * 64 + ps];
        } else {
            v0 = D[o * HH + 2 * ps];
            v1 = D[o * HH + 2 * ps + 1];
        }
        uint32_t hi, lo;
        split_pair(v0, v1, hi, lo);
        int d = (c * 128 + o) * 64 + kkperm(ps);
        g_B2h[d] = hi;
        g_B2l[d] = lo;
    }
}

// --------- GEMM1: Bu = U @ B1^T  (mma.sync, 3x bf16) + fused chunk-ends ------
__global__ __launch_bounds__(256, 2) void gemm1_kernel(const float* __restrict__ u) {
    extern __shared__ uint32_t sm[];
    uint32_t* Ah = sm + O_AH;
    uint32_t* Al = sm + O_AL;
    uint32_t* Bh = sm + O_BH;
    uint32_t* Bl = sm + O_BL;

    const int lt   = blockIdx.x;          // chunk index == l-tile
    const int b    = blockIdx.y;
    const int tid  = threadIdx.x;
    const int wid  = tid >> 5;
    const int lane = tid & 31;
    const int g    = lane >> 2;
    const int tq   = lane & 3;
    const int l0   = lt * 128;
    const int wr   = (wid & 3) * 32;
    const int wc   = (wid >> 2) * 32;

    // pack A tile: U[128 l x 128 h] -> hi/lo bf16x2, permuted
    {
        const float* ut = u + ((size_t)b * LL + l0) * HH;
        #pragma unroll
        for (int i = 0; i < 32; ++i) {
            int p  = tid + 256 * i;
            int row = p >> 6, ps = p & 63;
            float2 v = *(const float2*)(ut + row * HH + 2 * ps);
            uint32_t hi, lo;
            split_pair(v.x, v.y, hi, lo);
            int kk = kkperm(ps);
            Ah[row * STR + kk] = hi;
            Al[row * STR + kk] = lo;
        }
    }
    __syncthreads();

    for (int cc = 0; cc < 8; ++cc) {
        {
            const uint32_t* gh = g_B1h + cc * 64 * 64;
            const uint32_t* gl = g_B1l + cc * 64 * 64;
            #pragma unroll
            for (int i = 0; i < 16; ++i) {
                int p = tid + 256 * i;
                int col = p >> 6, kk = p & 63;
                Bh[col * STR + kk] = gh[p];
                Bl[col * STR + kk] = gl[p];
            }
        }
        __syncthreads();

        float acc[2][4][4];
        #pragma unroll
        for (int mf = 0; mf < 2; ++mf)
            #pragma unroll
            for (int nf = 0; nf < 4; ++nf)
                #pragma unroll
                for (int q = 0; q < 4; ++q) acc[mf][nf][q] = 0.f;

        #pragma unroll 1
        for (int K = 0; K < 8; ++K) {
            const int kb = K * 8 + 2 * tq;
            uint32_t ah[2][4], al[2][4];
            #pragma unroll
            for (int mf = 0; mf < 2; ++mf) {
                int r = wr + mf * 16 + g;
                uint2 t0 = lds64(&Ah[r * STR + kb]);
                uint2 t1 = lds64(&Ah[(r + 8) * STR + kb]);
                ah[mf][0] = t0.x; ah[mf][2] = t0.y;
                ah[mf][1] = t1.x; ah[mf][3] = t1.y;
                uint2 s0 = lds64(&Al[r * STR + kb]);
                uint2 s1 = lds64(&Al[(r + 8) * STR + kb]);
                al[mf][0] = s0.x; al[mf][2] = s0.y;
                al[mf][1] = s1.x; al[mf][3] = s1.y;
            }
            #pragma unroll
            for (int nf = 0; nf < 4; ++nf) {
                int cr = wc + nf * 8 + g;
                uint2 bh = lds64(&Bh[cr * STR + kb]);
                uint2 bl = lds64(&Bl[cr * STR + kb]);
                #pragma unroll
                for (int mf = 0; mf < 2; ++mf) {
                    mma16816(acc[mf][nf], ah[mf][0], ah[mf][1], ah[mf][2], ah[mf][3], bh.x, bh.y);
                    mma16816(acc[mf][nf], ah[mf][0], ah[mf][1], ah[mf][2], ah[mf][3], bl.x, bl.y);
                    mma16816(acc[mf][nf], al[mf][0], al[mf][1], al[mf][2], al[mf][3], bh.x, bh.y);
                }
            }
        }

        // epilogue: (re,im) pairs -> g_BuF
        {
            float* dst = g_BuF + ((size_t)b * LL + l0) * 512 + cc * 64;
            #pragma unroll
            for (int mf = 0; mf < 2; ++mf) {
                int row = wr + mf * 16 + g;
                #pragma unroll
                for (int nf = 0; nf < 4; ++nf) {
                    int col = wc + nf * 8 + 2 * tq;
                    *(float2*)&dst[(size_t)row * 512 + col] =
                        make_float2(acc[mf][nf][0], acc[mf][nf][1]);
                    *(float2*)&dst[(size_t)(row + 8) * 512 + col] =
                        make_float2(acc[mf][nf][2], acc[mf][nf][3]);
                }
            }
        }
        __syncthreads();
    }

    // ---- fused chunk-end scan: re-read own tile (L2-hot), reduce to g_end ----
    {
        const int n = tid;   // state index 0..255
        const float2 lam = g_lam[n];
        const float2* bu = (const float2*)g_BuF + ((size_t)b * LL + l0) * NN + n;
        float2 x = make_float2(0.f, 0.f);
        #pragma unroll 1
        for (int j0 = 0; j0 < TCH; j0 += 8) {
            float2 v[8];
            #pragma unroll
            for (int j = 0; j < 8; ++j) v[j] = bu[(size_t)(j0 + j) * NN];
            #pragma unroll
            for (int j = 0; j < 8; ++j) {
                float nr = fmaf(lam.x, x.x, fmaf(-lam.y, x.y, v[j].x));
                float ni = fmaf(lam.x, x.y, fmaf( lam.y, x.x, v[j].y));
                x = make_float2(nr, ni);
            }
        }
        g_end[((size_t)b * NCH + lt) * NN + n] = x;
    }
}

// ------- scan: carry prologue (weighted sum of ends) + final scan ------------
__global__ __launch_bounds__(256) void scan_kernel(float2* __restrict__ preOut,
                                                   size_t bstr,
                                                   float* __restrict__ str,
                                                   int writeFinal) {
    const int c = blockIdx.x;
    const int b = blockIdx.y;
    const int n = threadIdx.x;
    const float2 lam = g_lam[n];

    // carry[c] = sum_{j<c} lamT^(c-1-j) * end[j]   (independent loads, no chain)
    float2 x = make_float2(0.f, 0.f);
    for (int j = 0; j < c; ++j) {
        float2 e = g_end[((size_t)b * NCH + j) * NN + n];
        float2 p = g_lamP[(c - 1 - j) * NN + n];
        x.x = fmaf(p.x, e.x, fmaf(-p.y, e.y, x.x));
        x.y = fmaf(p.x, e.y, fmaf( p.y, e.x, x.y));
    }

    const int l0 = c * TCH;
    const float2* bu = (const float2*)g_BuF + ((size_t)b * LL + l0) * NN + n;
    float2* po = preOut + ((size_t)b * bstr + l0) * NN + n;
    float*  so = str ? str + ((size_t)b * (LL + 1) + l0) * NN + n : nullptr;
    #pragma unroll 4
    for (int j = 0; j < TCH; ++j) {
        po[(size_t)j * NN] = x;
        if (so) so[(size_t)j * NN] = x.x;
        float2 v = bu[(size_t)j * NN];
        float nr = fmaf(lam.x, x.x, fmaf(-lam.y, x.y, v.x));
        float ni = fmaf(lam.x, x.y, fmaf( lam.y, x.x, v.y));
        x = make_float2(nr, ni);
    }
    if (c == NCH - 1) {
        if (writeFinal) po[(size_t)TCH * NN] = x;
        if (so) so[(size_t)TCH * NN] = x.x;
    }
}

// ------------- GEMM2: y = Pre @ C~^T + U @ D^T  (mma.sync, 3x bf16) ----------
__global__ __launch_bounds__(256, 2) void gemm2_kernel(const float* __restrict__ u,
                                                       const float* __restrict__ preF,
                                                       size_t bstr,
                                                       float* __restrict__ yout) {
    extern __shared__ uint32_t sm[];
    uint32_t* Ah = sm + O_AH;
    uint32_t* Al = sm + O_AL;
    uint32_t* Bh = sm + O_BH;
    uint32_t* Bl = sm + O_BL;

    const int lt   = blockIdx.x;
    const int b    = blockIdx.y;
    const int tid  = threadIdx.x;
    const int wid  = tid >> 5;
    const int lane = tid & 31;
    const int g    = lane >> 2;
    const int tq   = lane & 3;
    const int l0   = lt * 128;
    const int wr   = (wid & 3) * 32;
    const int wc   = (wid >> 2) * 32;

    float acc[2][2][4][4];
    #pragma unroll
    for (int cc = 0; cc < 2; ++cc)
        #pragma unroll
        for (int mf = 0; mf < 2; ++mf)
            #pragma unroll
            for (int nf = 0; nf < 4; ++nf)
                #pragma unroll
                for (int q = 0; q < 4; ++q) acc[cc][mf][nf][q] = 0.f;

    for (int kc = 0; kc < 5; ++kc) {
        {
            #pragma unroll
            for (int i = 0; i < 32; ++i) {
                int p = tid + 256 * i;
                int row = p >> 6, ps = p & 63;
                float2 v;
                if (kc < 4)
                    v = *(const float2*)(preF + ((size_t)b * bstr + l0 + row) * 512
                                         + kc * 128 + 2 * ps);
                else
                    v = *(const float2*)(u + ((size_t)b * LL + l0 + row) * HH + 2 * ps);
                uint32_t hi, lo;
                split_pair(v.x, v.y, hi, lo);
                int kk = kkperm(ps);
                Ah[row * STR + kk] = hi;
                Al[row * STR + kk] = lo;
            }
        }
        for (int cc = 0; cc < 2; ++cc) {
            {
                const uint32_t* gh = g_B2h + (kc * 128 + cc * 64) * 64;
                const uint32_t* gl = g_B2l + (kc * 128 + cc * 64) * 64;
                #pragma unroll
                for (int i = 0; i < 16; ++i) {
                    int p = tid + 256 * i;
                    int col = p >> 6, kk = p & 63;
                    Bh[col * STR + kk] = gh[p];
                    Bl[col * STR + kk] = gl[p];
                }
            }
            __syncthreads();

            #pragma unroll 1
            for (int K = 0; K < 8; ++K) {
                const int kb = K * 8 + 2 * tq;
                uint32_t ah[2][4], al[2][4];
                #pragma unroll
                for (int mf = 0; mf < 2; ++mf) {
                    int r = wr + mf * 16 + g;
                    uint2 t0 = lds64(&Ah[r * STR + kb]);
                    uint2 t1 = lds64(&Ah[(r + 8) * STR + kb]);
                    ah[mf][0] = t0.x; ah[mf][2] = t0.y;
                    ah[mf][1] = t1.x; ah[mf][3] = t1.y;
                    uint2 s0 = lds64(&Al[r * STR + kb]);
                    uint2 s1 = lds64(&Al[(r + 8) * STR + kb]);
                    al[mf][0] = s0.x; al[mf][2] = s0.y;
                    al[mf][1] = s1.x; al[mf][3] = s1.y;
                }
                #pragma unroll
                for (int nf = 0; nf < 4; ++nf) {
                    int cr = wc + nf * 8 + g;
                    uint2 bh = lds64(&Bh[cr * STR + kb]);
                    uint2 bl = lds64(&Bl[cr * STR + kb]);
                    #pragma unroll
                    for (int mf = 0; mf < 2; ++mf) {
                        mma16816(acc[cc][mf][nf], ah[mf][0], ah[mf][1], ah[mf][2], ah[mf][3], bh.x, bh.y);
                        mma16816(acc[cc][mf][nf], ah[mf][0], ah[mf][1], ah[mf][2], ah[mf][3], bl.x, bl.y);
                        mma16816(acc[cc][mf][nf], al[mf][0], al[mf][1], al[mf][2], al[mf][3], bh.x, bh.y);
                    }
                }
            }
            __syncthreads();
        }
    }

    {
        float* dst = yout + ((size_t)b * LL + l0) * OO;
        #pragma unroll
        for (int cc = 0; cc < 2; ++cc)
            #pragma unroll
            for (int mf = 0; mf < 2; ++mf) {
                int row = wr + mf * 16 + g;
                #pragma unroll
                for (int nf = 0; nf < 4; ++nf) {
                    int col = cc * 64 + wc + nf * 8 + 2 * tq;
                    *(float2*)&dst[(size_t)row * OO + col] =
                        make_float2(acc[cc][mf][nf][0], acc[cc][mf][nf][1]);
                    *(float2*)&dst[(size_t)(row + 8) * OO + col] =
                        make_float2(acc[cc][mf][nf][2], acc[cc][mf][nf][3]);
                }
            }
    }
}

// ------------------------------ launch ---------------------------------------
extern "C" void kernel_launch(void* const* d_in, const int* in_sizes, int n_in,
                              void* d_out, int out_size) {
    const float* u         = (const float*)d_in[0];
    const float* nu_log    = (const float*)d_in[1];
    const float* theta_log = (const float*)d_in[2];
    const float* gamma_log = (const float*)d_in[3];
    const float* Bp_re     = (const float*)d_in[4];
    const float* Bp_im     = (const float*)d_in[5];
    const float* C_re      = (const float*)d_in[6];
    const float* C_im      = (const float*)d_in[7];
    const float* D         = (const float*)d_in[8];

    float* out = (float*)d_out;

    const long long NY  = (long long)BB * LL * OO;
    const long long NSc = (long long)BB * (LL + 1) * NN;
    const long long osz = (long long)out_size;

    float*  yout = nullptr;
    float2* stc  = nullptr;
    float*  str  = nullptr;

    if (osz == NY) {
        yout = out;
    } else if (osz == NY + 2 * NSc) {
        yout = out; stc = (float2*)(out + NY);
    } else if (osz == 2 * NSc) {
        stc = (float2*)out;
    } else if (osz == NSc) {
        stc = (float2*)out;
    } else if (osz == NY + NSc) {
        yout = out; str = out + NY;
    } else {
        yout = out;
    }

    cudaFuncSetAttribute(gemm1_kernel, cudaFuncAttributeMaxDynamicSharedMemorySize, SMEM_B);
    cudaFuncSetAttribute(gemm2_kernel, cudaFuncAttributeMaxDynamicSharedMemorySize, SMEM_B);

    prep_kernel<<<192, 256>>>(nu_log, theta_log, gamma_log,
                              Bp_re, Bp_im, C_re, C_im, D);
    gemm1_kernel<<<dim3(LL / 128, BB), 256, SMEM_B>>>(u);

    float2* preDev;
    size_t  bstr;
    if (stc) {
        preDev = stc;
        bstr   = (size_t)(LL + 1);
    } else {
        void* p = nullptr;
        cudaGetSymbolAddress(&p, g_states);
        preDev = (float2*)p;
        bstr   = (size_t)LL;
    }

    scan_kernel<<<dim3(NCH, BB), 256>>>(preDev, bstr, str, stc ? 1 : 0);

    if (yout)
        gemm2_kernel<<<dim3(LL / 128, BB), 256, SMEM_B>>>(u, (const float*)preDev,
                                                          bstr, yout);
}

// round 7
// speedup vs baseline: 3.7723x; 1.4264x over previous
#include <cuda_runtime.h>
#include <cuda_bf16.h>
#include <cstdint>

// ---------------------------------------------------------------------------
// LRU forward on GB300, round 6: mma.sync bf16-3-split GEMMs with conflict-free
// XOR-swizzled smem (fixes 4-way LDS bank conflicts of round 5).
//   gemm1: Bu = U @ B1^T  (+ fused per-chunk local scan -> g_end)
//   scan:  carry prologue (lamT-power weighted sum of ends) + final scan
//   gemm2: y = Pre @ C~^T + U @ D^T   (K = 640, 5 chunks)
// ---------------------------------------------------------------------------

#define BB   8
#define LL   8192
#define HH   128
#define NN   256
#define OO   128
#define TCH  128
#define NCH  (LL / TCH)   // 64

// smem layout (u32 units), row stride 64, XOR-swizzled
#define O_AH 0
#define O_AL (128 * 64)
#define O_BH (2 * 128 * 64)
#define O_BL (2 * 128 * 64 + 64 * 64)
#define SMEM_U32 (2 * 128 * 64 + 2 * 64 * 64)        // 24576 u32
#define SMEM_B   (SMEM_U32 * 4)                      // 98304 bytes

// ------------------------- scratch (static device) -------------------------
__device__ float    g_BuF[(size_t)BB * LL * 512];    // 134 MB, (re,im) interleaved
__device__ float2   g_states[(size_t)BB * LL * NN];  // 128 MB pre-states fallback
__device__ float2   g_lam[NN];
__device__ float2   g_lamP[NCH * NN];                // lamT^k, k = 0..63
__device__ float2   g_end[BB * NCH * NN];
// pre-packed, swizzled B images (u32 = bf16x2)
__device__ uint32_t g_B1h[512 * 64];
__device__ uint32_t g_B1l[512 * 64];
__device__ uint32_t g_B2h[5 * 128 * 64];
__device__ uint32_t g_B2l[5 * 128 * 64];

// ------------------------------ helpers -------------------------------------
// fragment permutation within an 8-pair (k16) block: pair p -> (p&3)*2 + (p>>2)
__device__ __forceinline__ int kkperm(int ps) {
    return (ps & ~7) + ((ps & 3) * 2 + ((ps >> 2) & 1));
}
// conflict-free slot: XOR bits [3:4] with row&3 (8B-granular swizzle)
__device__ __forceinline__ int kkslot(int row, int ps) {
    return kkperm(ps) ^ ((row & 3) << 3);
}

__device__ __forceinline__ void split_pair(float v0, float v1,
                                           uint32_t& hi, uint32_t& lo) {
    __nv_bfloat16 h0 = __float2bfloat16(v0);
    __nv_bfloat16 h1 = __float2bfloat16(v1);
    __nv_bfloat16 l0 = __float2bfloat16(v0 - __bfloat162float(h0));
    __nv_bfloat16 l1 = __float2bfloat16(v1 - __bfloat162float(h1));
    hi = (uint32_t)__bfloat16_as_ushort(h0) | ((uint32_t)__bfloat16_as_ushort(h1) << 16);
    lo = (uint32_t)__bfloat16_as_ushort(l0) | ((uint32_t)__bfloat16_as_ushort(l1) << 16);
}

__device__ __forceinline__ void mma16816(float* d,
                                         uint32_t a0, uint32_t a1, uint32_t a2, uint32_t a3,
                                         uint32_t b0, uint32_t b1) {
    asm volatile("mma.sync.aligned.m16n8k16.row.col.f32.bf16.bf16.f32 "
                 "{%0,%1,%2,%3},{%4,%5,%6,%7},{%8,%9},{%0,%1,%2,%3};"
                 : "+f"(d[0]), "+f"(d[1]), "+f"(d[2]), "+f"(d[3])
                 : "r"(a0), "r"(a1), "r"(a2), "r"(a3), "r"(b0), "r"(b1));
}

__device__ __forceinline__ uint2 lds64(const uint32_t* p) {
    return *(const uint2*)p;
}

// ------------------------------- prep ---------------------------------------
__global__ void prep_kernel(const float* __restrict__ nu_log,
                            const float* __restrict__ theta_log,
                            const float* __restrict__ gamma_log,
                            const float* __restrict__ Bp_re,
                            const float* __restrict__ Bp_im,
                            const float* __restrict__ C_re,
                            const float* __restrict__ C_im,
                            const float* __restrict__ D) {
    int idx = blockIdx.x * blockDim.x + threadIdx.x;   // 0..49151

    if (idx < NN) {
        float nu = expf(nu_log[idx]);
        float a  = expf(-nu);
        float th = expf(theta_log[idx]);
        g_lam[idx] = make_float2(a * cosf(th), a * sinf(th));
    }
    if (idx < NCH * NN) {   // lamT^k (double-precision powers)
        int k = idx >> 8;
        int n = idx & (NN - 1);
        double nu = exp((double)nu_log[n]);
        double th = exp((double)theta_log[n]);
        double r   = exp(-nu * (double)TCH * (double)k);
        double ang = th * (double)TCH * (double)k;
        g_lamP[idx] = make_float2((float)(r * cos(ang)), (float)(r * sin(ang)));
    }
    // B1: 512 rows (r = 2n+im) x 64 k-pairs, chunked by 64 rows
    if (idx < 512 * 64) {
        int r  = idx >> 6;
        int ps = idx & 63;
        int n  = r >> 1;
        int im = r & 1;
        float g = expf(gamma_log[n]);
        const float* src = im ? Bp_im : Bp_re;
        float v0 = g * src[n * HH + 2 * ps];
        float v1 = g * src[n * HH + 2 * ps + 1];
        uint32_t hi, lo;
        split_pair(v0, v1, hi, lo);
        int d = r * 64 + kkslot(r, ps);   // r&3 == (r&63)&3: chunk-local consistent
        g_B1h[d] = hi;
        g_B1l[d] = lo;
    }
    // B2: 5 k-chunks x 128 rows (o) x 64 k-pairs
    if (idx < 5 * 128 * 64) {
        int c  = idx >> 13;
        int o  = (idx >> 6) & 127;
        int ps = idx & 63;
        float v0, v1;
        if (c < 4) {
            v0 =  C_re[o * NN + c * 64 + ps];
            v1 = -C_im[o * NN + c * 64 + ps];
        } else {
            v0 = D[o * HH + 2 * ps];
            v1 = D[o * HH + 2 * ps + 1];
        }
        uint32_t hi, lo;
        split_pair(v0, v1, hi, lo);
        int d = (c * 128 + o) * 64 + kkslot(o, ps);
        g_B2h[d] = hi;
        g_B2l[d] = lo;
    }
}

// --------- GEMM1: Bu = U @ B1^T  (mma.sync, 3x bf16) + fused chunk-ends ------
__global__ __launch_bounds__(256, 2) void gemm1_kernel(const float* __restrict__ u) {
    extern __shared__ uint32_t sm[];
    uint32_t* Ah = sm + O_AH;
    uint32_t* Al = sm + O_AL;
    uint32_t* Bh = sm + O_BH;
    uint32_t* Bl = sm + O_BL;

    const int lt   = blockIdx.x;          // chunk index == l-tile
    const int b    = blockIdx.y;
    const int tid  = threadIdx.x;
    const int wid  = tid >> 5;
    const int lane = tid & 31;
    const int g    = lane >> 2;
    const int tq   = lane & 3;
    const int xr   = (g & 3) << 3;        // per-thread swizzle constant
    const int l0   = lt * 128;
    const int wr   = (wid & 3) * 32;
    const int wc   = (wid >> 2) * 32;

    // pack A tile: U[128 l x 128 h] -> hi/lo bf16x2, swizzled
    {
        const float* ut = u + ((size_t)b * LL + l0) * HH;
        #pragma unroll
        for (int i = 0; i < 32; ++i) {
            int p  = tid + 256 * i;
            int row = p >> 6, ps = p & 63;
            float2 v = *(const float2*)(ut + row * HH + 2 * ps);
            uint32_t hi, lo;
            split_pair(v.x, v.y, hi, lo);
            int kk = kkslot(row, ps);
            Ah[row * 64 + kk] = hi;
            Al[row * 64 + kk] = lo;
        }
    }
    __syncthreads();

    for (int cc = 0; cc < 8; ++cc) {
        // identity copy of pre-swizzled B chunk
        {
            const uint32_t* gh = g_B1h + cc * 64 * 64;
            const uint32_t* gl = g_B1l + cc * 64 * 64;
            #pragma unroll
            for (int i = 0; i < 16; ++i) {
                int p = tid + 256 * i;
                Bh[p] = gh[p];
                Bl[p] = gl[p];
            }
        }
        __syncthreads();

        float acc[2][4][4];
        #pragma unroll
        for (int mf = 0; mf < 2; ++mf)
            #pragma unroll
            for (int nf = 0; nf < 4; ++nf)
                #pragma unroll
                for (int q = 0; q < 4; ++q) acc[mf][nf][q] = 0.f;

        #pragma unroll 1
        for (int K = 0; K < 8; ++K) {
            const int kb = (K * 8 + 2 * tq) ^ xr;
            uint32_t ah[2][4], al[2][4];
            #pragma unroll
            for (int mf = 0; mf < 2; ++mf) {
                int r = wr + mf * 16 + g;
                uint2 t0 = lds64(&Ah[r * 64 + kb]);
                uint2 t1 = lds64(&Ah[(r + 8) * 64 + kb]);
                ah[mf][0] = t0.x; ah[mf][2] = t0.y;
                ah[mf][1] = t1.x; ah[mf][3] = t1.y;
                uint2 s0 = lds64(&Al[r * 64 + kb]);
                uint2 s1 = lds64(&Al[(r + 8) * 64 + kb]);
                al[mf][0] = s0.x; al[mf][2] = s0.y;
                al[mf][1] = s1.x; al[mf][3] = s1.y;
            }
            #pragma unroll
            for (int nf = 0; nf < 4; ++nf) {
                int cr = wc + nf * 8 + g;
                uint2 bh = lds64(&Bh[cr * 64 + kb]);
                uint2 bl = lds64(&Bl[cr * 64 + kb]);
                #pragma unroll
                for (int mf = 0; mf < 2; ++mf) {
                    mma16816(acc[mf][nf], ah[mf][0], ah[mf][1], ah[mf][2], ah[mf][3], bh.x, bh.y);
                    mma16816(acc[mf][nf], ah[mf][0], ah[mf][1], ah[mf][2], ah[mf][3], bl.x, bl.y);
                    mma16816(acc[mf][nf], al[mf][0], al[mf][1], al[mf][2], al[mf][3], bh.x, bh.y);
                }
            }
        }

        // epilogue: (re,im) pairs -> g_BuF
        {
            float* dst = g_BuF + ((size_t)b * LL + l0) * 512 + cc * 64;
            #pragma unroll
            for (int mf = 0; mf < 2; ++mf) {
                int row = wr + mf * 16 + g;
                #pragma unroll
                for (int nf = 0; nf < 4; ++nf) {
                    int col = wc + nf * 8 + 2 * tq;
                    *(float2*)&dst[(size_t)row * 512 + col] =
                        make_float2(acc[mf][nf][0], acc[mf][nf][1]);
                    *(float2*)&dst[(size_t)(row + 8) * 512 + col] =
                        make_float2(acc[mf][nf][2], acc[mf][nf][3]);
                }
            }
        }
        __syncthreads();
    }

    // ---- fused chunk-end scan: re-read own tile (L2-hot), reduce to g_end ----
    {
        const int n = tid;
        const float2 lam = g_lam[n];
        const float2* bu = (const float2*)g_BuF + ((size_t)b * LL + l0) * NN + n;
        float2 x = make_float2(0.f, 0.f);
        #pragma unroll 1
        for (int j0 = 0; j0 < TCH; j0 += 8) {
            float2 v[8];
            #pragma unroll
            for (int j = 0; j < 8; ++j) v[j] = bu[(size_t)(j0 + j) * NN];
            #pragma unroll
            for (int j = 0; j < 8; ++j) {
                float nr = fmaf(lam.x, x.x, fmaf(-lam.y, x.y, v[j].x));
                float ni = fmaf(lam.x, x.y, fmaf( lam.y, x.x, v[j].y));
                x = make_float2(nr, ni);
            }
        }
        g_end[((size_t)b * NCH + lt) * NN + n] = x;
    }
}

// ------- scan: carry prologue (weighted sum of ends) + final scan ------------
__global__ __launch_bounds__(256) void scan_kernel(float2* __restrict__ preOut,
                                                   size_t bstr,
                                                   float* __restrict__ str,
                                                   int writeFinal) {
    const int c = blockIdx.x;
    const int b = blockIdx.y;
    const int n = threadIdx.x;
    const float2 lam = g_lam[n];

    // carry[c] = sum_{j<c} lamT^(c-1-j) * end[j]
    float2 x = make_float2(0.f, 0.f);
    for (int j = 0; j < c; ++j) {
        float2 e = g_end[((size_t)b * NCH + j) * NN + n];
        float2 p = g_lamP[(c - 1 - j) * NN + n];
        x.x = fmaf(p.x, e.x, fmaf(-p.y, e.y, x.x));
        x.y = fmaf(p.x, e.y, fmaf( p.y, e.x, x.y));
    }

    const int l0 = c * TCH;
    const float2* bu = (const float2*)g_BuF + ((size_t)b * LL + l0) * NN + n;
    float2* po = preOut + ((size_t)b * bstr + l0) * NN + n;
    float*  so = str ? str + ((size_t)b * (LL + 1) + l0) * NN + n : nullptr;
    #pragma unroll 4
    for (int j = 0; j < TCH; ++j) {
        po[(size_t)j * NN] = x;
        if (so) so[(size_t)j * NN] = x.x;
        float2 v = bu[(size_t)j * NN];
        float nr = fmaf(lam.x, x.x, fmaf(-lam.y, x.y, v.x));
        float ni = fmaf(lam.x, x.y, fmaf( lam.y, x.x, v.y));
        x = make_float2(nr, ni);
    }
    if (c == NCH - 1) {
        if (writeFinal) po[(size_t)TCH * NN] = x;
        if (so) so[(size_t)TCH * NN] = x.x;
    }
}

// ------------- GEMM2: y = Pre @ C~^T + U @ D^T  (mma.sync, 3x bf16) ----------
__global__ __launch_bounds__(256, 2) void gemm2_kernel(const float* __restrict__ u,
                                                       const float* __restrict__ preF,
                                                       size_t bstr,
                                                       float* __restrict__ yout) {
    extern __shared__ uint32_t sm[];
    uint32_t* Ah = sm + O_AH;
    uint32_t* Al = sm + O_AL;
    uint32_t* Bh = sm + O_BH;
    uint32_t* Bl = sm + O_BL;

    const int lt   = blockIdx.x;
    const int b    = blockIdx.y;
    const int tid  = threadIdx.x;
    const int wid  = tid >> 5;
    const int lane = tid & 31;
    const int g    = lane >> 2;
    const int tq   = lane & 3;
    const int xr   = (g & 3) << 3;
    const int l0   = lt * 128;
    const int wr   = (wid & 3) * 32;
    const int wc   = (wid >> 2) * 32;

    float acc[2][2][4][4];
    #pragma unroll
    for (int cc = 0; cc < 2; ++cc)
        #pragma unroll
        for (int mf = 0; mf < 2; ++mf)
            #pragma unroll
            for (int nf = 0; nf < 4; ++nf)
                #pragma unroll
                for (int q = 0; q < 4; ++q) acc[cc][mf][nf][q] = 0.f;

    for (int kc = 0; kc < 5; ++kc) {
        // pack A chunk: pre-states (kc<4) or u (kc==4)
        {
            #pragma unroll
            for (int i = 0; i < 32; ++i) {
                int p = tid + 256 * i;
                int row = p >> 6, ps = p & 63;
                float2 v;
                if (kc < 4)
                    v = *(const float2*)(preF + ((size_t)b * bstr + l0 + row) * 512
                                         + kc * 128 + 2 * ps);
                else
                    v = *(const float2*)(u + ((size_t)b * LL + l0 + row) * HH + 2 * ps);
                uint32_t hi, lo;
                split_pair(v.x, v.y, hi, lo);
                int kk = kkslot(row, ps);
                Ah[row * 64 + kk] = hi;
                Al[row * 64 + kk] = lo;
            }
        }
        for (int cc = 0; cc < 2; ++cc) {
            {
                const uint32_t* gh = g_B2h + (kc * 128 + cc * 64) * 64;
                const uint32_t* gl = g_B2l + (kc * 128 + cc * 64) * 64;
                #pragma unroll
                for (int i = 0; i < 16; ++i) {
                    int p = tid + 256 * i;
                    Bh[p] = gh[p];
                    Bl[p] = gl[p];
                }
            }
            __syncthreads();

            #pragma unroll 1
            for (int K = 0; K < 8; ++K) {
                const int kb = (K * 8 + 2 * tq) ^ xr;
                uint32_t ah[2][4], al[2][4];
                #pragma unroll
                for (int mf = 0; mf < 2; ++mf) {
                    int r = wr + mf * 16 + g;
                    uint2 t0 = lds64(&Ah[r * 64 + kb]);
                    uint2 t1 = lds64(&Ah[(r + 8) * 64 + kb]);
                    ah[mf][0] = t0.x; ah[mf][2] = t0.y;
                    ah[mf][1] = t1.x; ah[mf][3] = t1.y;
                    uint2 s0 = lds64(&Al[r * 64 + kb]);
                    uint2 s1 = lds64(&Al[(r + 8) * 64 + kb]);
                    al[mf][0] = s0.x; al[mf][2] = s0.y;
                    al[mf][1] = s1.x; al[mf][3] = s1.y;
                }
                #pragma unroll
                for (int nf = 0; nf < 4; ++nf) {
                    int cr = wc + nf * 8 + g;
                    uint2 bh = lds64(&Bh[cr * 64 + kb]);
                    uint2 bl = lds64(&Bl[cr * 64 + kb]);
                    #pragma unroll
                    for (int mf = 0; mf < 2; ++mf) {
                        mma16816(acc[cc][mf][nf], ah[mf][0], ah[mf][1], ah[mf][2], ah[mf][3], bh.x, bh.y);
                        mma16816(acc[cc][mf][nf], ah[mf][0], ah[mf][1], ah[mf][2], ah[mf][3], bl.x, bl.y);
                        mma16816(acc[cc][mf][nf], al[mf][0], al[mf][1], al[mf][2], al[mf][3], bh.x, bh.y);
                    }
                }
            }
            __syncthreads();
        }
    }

    {
        float* dst = yout + ((size_t)b * LL + l0) * OO;
        #pragma unroll
        for (int cc = 0; cc < 2; ++cc)
            #pragma unroll
            for (int mf = 0; mf < 2; ++mf) {
                int row = wr + mf * 16 + g;
                #pragma unroll
                for (int nf = 0; nf < 4; ++nf) {
                    int col = cc * 64 + wc + nf * 8 + 2 * tq;
                    *(float2*)&dst[(size_t)row * OO + col] =
                        make_float2(acc[cc][mf][nf][0], acc[cc][mf][nf][1]);
                    *(float2*)&dst[(size_t)(row + 8) * OO + col] =
                        make_float2(acc[cc][mf][nf][2], acc[cc][mf][nf][3]);
                }
            }
    }
}

// ------------------------------ launch ---------------------------------------
extern "C" void kernel_launch(void* const* d_in, const int* in_sizes, int n_in,
                              void* d_out, int out_size) {
    const float* u         = (const float*)d_in[0];
    const float* nu_log    = (const float*)d_in[1];
    const float* theta_log = (const float*)d_in[2];
    const float* gamma_log = (const float*)d_in[3];
    const float* Bp_re     = (const float*)d_in[4];
    const float* Bp_im     = (const float*)d_in[5];
    const float* C_re      = (const float*)d_in[6];
    const float* C_im      = (const float*)d_in[7];
    const float* D         = (const float*)d_in[8];

    float* out = (float*)d_out;

    const long long NY  = (long long)BB * LL * OO;
    const long long NSc = (long long)BB * (LL + 1) * NN;
    const long long osz = (long long)out_size;

    float*  yout = nullptr;
    float2* stc  = nullptr;
    float*  str  = nullptr;

    if (osz == NY) {
        yout = out;
    } else if (osz == NY + 2 * NSc) {
        yout = out; stc = (float2*)(out + NY);
    } else if (osz == 2 * NSc) {
        stc = (float2*)out;
    } else if (osz == NSc) {
        stc = (float2*)out;
    } else if (osz == NY + NSc) {
        yout = out; str = out + NY;
    } else {
        yout = out;
    }

    cudaFuncSetAttribute(gemm1_kernel, cudaFuncAttributeMaxDynamicSharedMemorySize, SMEM_B);
    cudaFuncSetAttribute(gemm2_kernel, cudaFuncAttributeMaxDynamicSharedMemorySize, SMEM_B);

    prep_kernel<<<192, 256>>>(nu_log, theta_log, gamma_log,
                              Bp_re, Bp_im, C_re, C_im, D);
    gemm1_kernel<<<dim3(LL / 128, BB), 256, SMEM_B>>>(u);

    float2* preDev;
    size_t  bstr;
    if (stc) {
        preDev = stc;
        bstr   = (size_t)(LL + 1);
    } else {
        void* p = nullptr;
        cudaGetSymbolAddress(&p, g_states);
        preDev = (float2*)p;
        bstr   = (size_t)LL;
    }

    scan_kernel<<<dim3(NCH, BB), 256>>>(preDev, bstr, str, stc ? 1 : 0);

    if (yout)
        gemm2_kernel<<<dim3(LL / 128, BB), 256, SMEM_B>>>(u, (const float*)preDev,
                                                          bstr, yout);
}